// round 1
// baseline (speedup 1.0000x reference)
#include <cuda_runtime.h>

// ---------------- problem constants ----------------
#define BN   16
#define CH   128
#define HWN  1024
#define SN   8
#define SBN  128
#define CHW  131072        // CH*HWN

// ---------------- device scratch ----------------
__device__ float g_ht [BN*CHW];
__device__ float g_q  [BN*CHW];
__device__ float g_k  [SBN*CHW];
__device__ float g_v  [SBN*CHW];
__device__ float g_av [BN*CHW];
__device__ float g_att[BN*CHW];
__device__ float g_o  [BN*CHW];
__device__ float g_stats[2*SBN];
__device__ float g_pool[SBN*2*HWN];
__device__ float g_qsa[BN*HWN];
__device__ float g_ksa[SBN*HWN];
__device__ float g_qfg[SN*BN*CH];
__device__ float g_sprob[SBN*HWN];
__device__ float g_tl[SN*BN];
__device__ float g_tp[SN*BN];
__device__ float g_peN[SN*2*CH];
__device__ float g_se1[BN*CH];
__device__ float g_se2[BN*32];
__device__ float g_se3[BN*CH];
__device__ float g_wT[1048576];   // transposed weights, see offsets in host code

__device__ __forceinline__ float sigmf(float x){ return 1.f/(1.f + __expf(-x)); }

// mask may arrive as 1-byte bool or 4-byte int/float. Detect element width.
__device__ __forceinline__ bool mask_at(const unsigned char* m, int b){
    if (m[1] != 0) return m[b] != 0;                 // 1-byte bools (all-true setup)
    const unsigned int* w = (const unsigned int*)m;  // 4-byte elements
    return w[b] != 0;
}

// ---------------- weight transpose: (Cout,Cin,kh,kw) -> [c][tap][co] ----------------
__global__ void transw_k(const float* __restrict__ w, float* __restrict__ wT,
                         int cin, int ktaps)
{
    int n = cin*ktaps*128;
    for (int i = blockIdx.x*blockDim.x + threadIdx.x; i < n; i += gridDim.x*blockDim.x){
        int co = i & 127;
        int r  = i >> 7;
        int tap = r % ktaps;
        int c   = r / ktaps;
        wT[i] = w[(co*cin + c)*ktaps + tap];
    }
}

// ---------------- pos_emb row normalization ----------------
__global__ void pe_norm_k(const float* __restrict__ pe, float* __restrict__ peN)
{
    int s = blockIdx.x;          // 8 rows
    int t = threadIdx.x;         // 256
    float v = pe[s*256 + t];
    float q = v*v;
    #pragma unroll
    for (int o=16;o;o>>=1) q += __shfl_down_sync(0xffffffffu, q, o);
    __shared__ float a[8];
    __shared__ float fac;
    if ((t&31)==0) a[t>>5] = q;
    __syncthreads();
    if (t==0){
        float S=0.f;
        #pragma unroll
        for (int i=0;i<8;i++) S += a[i];
        float n = sqrtf(S);
        fac = fminf(1.f, 1.f/fmaxf(n, 1e-7f));
    }
    __syncthreads();
    peN[s*256 + t] = v*fac;
}

// ---------------- generic 3x3 conv, pad=1, Cout=128 ----------------
// modes: 0 = single source (cin from s0)
//        1 = concat(s0[128], s1[128])           (kv)
//        2 = concat + pe add (s2 = peN[S][256]) (kv + pe)
//        3 = concat(s0 inputs[64], s1[128]+s2[128]) (outt input)
__global__ __launch_bounds__(256,2)
void conv3x3_k(const float* __restrict__ s0, const float* __restrict__ s1,
               const float* __restrict__ s2, const float* __restrict__ wT,
               float* __restrict__ dst, int cin, int mode)
{
    __shared__ float sIn[8*6*34];
    __shared__ float sW [8*9*128];
    const int t   = threadIdx.x;
    const int img = blockIdx.x >> 3;
    const int y0  = (blockIdx.x & 7) << 2;
    const int x   = t & 31;
    const int cg  = t >> 5;

    float acc[64];
    #pragma unroll
    for (int i=0;i<64;i++) acc[i]=0.f;

    const int nchunk = cin >> 3;
    for (int cc=0; cc<nchunk; cc++){
        const float* wp = wT + cc*9216;
        for (int e=t; e<9216; e+=256) sW[e] = wp[e];
        for (int e=t; e<1632; e+=256){
            int ci = e/204; int rem = e - ci*204;
            int r  = rem/34; int xx = rem - r*34;
            int y  = y0 - 1 + r; int xg = xx - 1;
            float val = 0.f;
            if ((unsigned)y < 32u && (unsigned)xg < 32u){
                int c = (cc<<3) + ci;
                int p = (y<<5) + xg;
                if (mode == 0){
                    val = s0[((size_t)img*cin + c)*1024 + p];
                } else if (mode == 1){
                    val = (c < 128) ? s0[((size_t)img*128 + c)*1024 + p]
                                    : s1[((size_t)img*128 + (c-128))*1024 + p];
                } else if (mode == 2){
                    float bv = (c < 128) ? s0[((size_t)img*128 + c)*1024 + p]
                                         : s1[((size_t)img*128 + (c-128))*1024 + p];
                    val = bv + s2[(img>>4)*256 + c];
                } else {
                    val = (c < 64) ? s0[((size_t)img*64 + c)*1024 + p]
                                   : s1[((size_t)img*128 + (c-64))*1024 + p]
                                   + s2[((size_t)img*128 + (c-64))*1024 + p];
                }
            }
            sIn[(ci*6 + r)*34 + xx] = val;
        }
        __syncthreads();
        #pragma unroll 1
        for (int ci=0; ci<8; ci++){
            float inr[18];
            #pragma unroll
            for (int r=0;r<6;r++){
                #pragma unroll
                for (int d=0;d<3;d++) inr[r*3+d] = sIn[(ci*6+r)*34 + x + d];
            }
            #pragma unroll
            for (int tap=0; tap<9; tap++){
                const int dy = tap/3, dx = tap - dy*3;
                const float4* wq = (const float4*)&sW[(ci*9+tap)*128 + (cg<<4)];
                float4 w0 = wq[0], w1 = wq[1], w2 = wq[2], w3 = wq[3];
                #pragma unroll
                for (int y=0;y<4;y++){
                    float iv = inr[(y+dy)*3 + dx];
                    float* a = &acc[y*16];
                    a[0]  += iv*w0.x; a[1]  += iv*w0.y; a[2]  += iv*w0.z; a[3]  += iv*w0.w;
                    a[4]  += iv*w1.x; a[5]  += iv*w1.y; a[6]  += iv*w1.z; a[7]  += iv*w1.w;
                    a[8]  += iv*w2.x; a[9]  += iv*w2.y; a[10] += iv*w2.z; a[11] += iv*w2.w;
                    a[12] += iv*w3.x; a[13] += iv*w3.y; a[14] += iv*w3.z; a[15] += iv*w3.w;
                }
            }
        }
        __syncthreads();
    }
    #pragma unroll
    for (int j=0;j<16;j++){
        int co = (cg<<4) + j;
        #pragma unroll
        for (int y=0;y<4;y++)
            dst[((size_t)img*128 + co)*1024 + ((y0+y)<<5) + x] = acc[y*16+j];
    }
}

// ---------------- 1x1 conv (vpost), 128->128 ----------------
__global__ __launch_bounds__(256,2)
void conv1x1_k(const float* __restrict__ src, const float* __restrict__ wT,
               float* __restrict__ dst)
{
    __shared__ float sIn[8*128];
    __shared__ float sW [8*128];
    const int t   = threadIdx.x;
    const int img = blockIdx.x >> 3;
    const int p0  = (blockIdx.x & 7) << 7;
    const int xl  = t & 31;
    const int cg  = t >> 5;
    float acc[64];
    #pragma unroll
    for (int i=0;i<64;i++) acc[i]=0.f;

    for (int cc=0; cc<16; cc++){
        for (int e=t; e<1024; e+=256){
            int ci = e>>7, i = e&127;
            sIn[e] = src[((size_t)img*128 + (cc<<3)+ci)*1024 + p0 + i];
            sW [e] = wT[(cc<<10) + e];
        }
        __syncthreads();
        #pragma unroll
        for (int ci=0;ci<8;ci++){
            float inr[4];
            #pragma unroll
            for (int y=0;y<4;y++) inr[y] = sIn[ci*128 + (y<<5) + xl];
            const float4* wq = (const float4*)&sW[ci*128 + (cg<<4)];
            float4 w0=wq[0], w1=wq[1], w2=wq[2], w3=wq[3];
            #pragma unroll
            for (int y=0;y<4;y++){
                float iv = inr[y];
                float* a = &acc[y*16];
                a[0]  += iv*w0.x; a[1]  += iv*w0.y; a[2]  += iv*w0.z; a[3]  += iv*w0.w;
                a[4]  += iv*w1.x; a[5]  += iv*w1.y; a[6]  += iv*w1.z; a[7]  += iv*w1.w;
                a[8]  += iv*w2.x; a[9]  += iv*w2.y; a[10] += iv*w2.z; a[11] += iv*w2.w;
                a[12] += iv*w3.x; a[13] += iv*w3.y; a[14] += iv*w3.z; a[15] += iv*w3.w;
            }
        }
        __syncthreads();
    }
    #pragma unroll
    for (int j=0;j<16;j++){
        int co = (cg<<4)+j;
        #pragma unroll
        for (int y=0;y<4;y++)
            dst[((size_t)img*128+co)*1024 + p0 + (y<<5) + xl] = acc[y*16+j];
    }
}

// ---------------- GroupNorm(groups=1): per-sample mean/rstd over C*H*W ----------------
__global__ void gn_reduce_k(const float* __restrict__ x, float* __restrict__ stats)
{
    const int img = blockIdx.x;
    const float4* p = (const float4*)(x + (size_t)img*CHW);
    float s=0.f, s2=0.f;
    for (int i=threadIdx.x; i<32768; i+=blockDim.x){
        float4 v = p[i];
        s  += v.x+v.y+v.z+v.w;
        s2 += v.x*v.x+v.y*v.y+v.z*v.z+v.w*v.w;
    }
    #pragma unroll
    for (int o=16;o;o>>=1){
        s  += __shfl_down_sync(0xffffffffu, s , o);
        s2 += __shfl_down_sync(0xffffffffu, s2, o);
    }
    __shared__ float sa[8], sb[8];
    if ((threadIdx.x&31)==0){ sa[threadIdx.x>>5]=s; sb[threadIdx.x>>5]=s2; }
    __syncthreads();
    if (threadIdx.x==0){
        float S=0.f, S2=0.f;
        #pragma unroll
        for (int i=0;i<8;i++){ S+=sa[i]; S2+=sb[i]; }
        float mu  = S*(1.f/131072.f);
        float var = S2*(1.f/131072.f) - mu*mu;
        stats[img*2]   = mu;
        stats[img*2+1] = rsqrtf(var + 1e-5f);
    }
}

__global__ void gn_apply_k(float* __restrict__ x, const float* __restrict__ stats,
                           const float* __restrict__ gw, const float* __restrict__ gb,
                           int nimg, int act)
{
    int n4 = nimg*32768;
    for (int i = blockIdx.x*blockDim.x + threadIdx.x; i < n4; i += gridDim.x*blockDim.x){
        int base = i<<2;
        int img = base>>17; int c = (base>>10)&127;
        float mu = stats[2*img], rs = stats[2*img+1];
        float sc = rs*gw[c];
        float sh = gb[c] - mu*sc;
        float4 v = ((float4*)x)[i];
        v.x = v.x*sc+sh; v.y = v.y*sc+sh; v.z = v.z*sc+sh; v.w = v.w*sc+sh;
        if (act){
            v.x *= sigmf(v.x); v.y *= sigmf(v.y); v.z *= sigmf(v.z); v.w *= sigmf(v.w);
        }
        ((float4*)x)[i] = v;
    }
}

// ---------------- channel mean/max pooling for spatial filters ----------------
__global__ void pool_k(const float* __restrict__ x, float* __restrict__ pool, int nimg)
{
    int i = blockIdx.x*blockDim.x + threadIdx.x;
    if (i >= nimg*HWN) return;
    int img = i>>10, p = i&1023;
    const float* base = x + (size_t)img*CHW + p;
    float s = 0.f, m = -3.402823466e38f;
    #pragma unroll 4
    for (int c=0;c<128;c++){
        float v = base[(size_t)c<<10];
        s += v; m = fmaxf(m, v);
    }
    pool[img*2048 + p]        = s*(1.f/128.f);
    pool[img*2048 + 1024 + p] = m;
}

// ---------------- 2->1 3x3 conv + sigmoid (spatial filter) ----------------
__global__ void saconv_k(const float* __restrict__ pool, const float* __restrict__ w,
                         const float* __restrict__ b, float* __restrict__ sa, int nimg)
{
    int i = blockIdx.x*blockDim.x + threadIdx.x;
    if (i >= nimg*HWN) return;
    int img = i>>10, p = i&1023, y = p>>5, x = p&31;
    float acc = b[0];
    #pragma unroll
    for (int c2=0;c2<2;c2++){
        #pragma unroll
        for (int dy=-1;dy<=1;dy++){
            #pragma unroll
            for (int dx=-1;dx<=1;dx++){
                int yy=y+dy, xx=x+dx;
                if ((unsigned)yy<32u && (unsigned)xx<32u)
                    acc += pool[img*2048 + c2*1024 + (yy<<5)+xx] * w[c2*9 + (dy+1)*3 + (dx+1)];
            }
        }
    }
    sa[i] = sigmf(acc);
}

// ---------------- q_fg[s,b,c] = mean_hw( k_sa[s,b,hw] * q[b,c,hw] ) ----------------
__global__ void qfg_k()
{
    int wid  = (blockIdx.x*blockDim.x + threadIdx.x) >> 5;
    int lane = threadIdx.x & 31;
    if (wid >= SN*BN*CH) return;
    int c = wid & 127, b = (wid>>7)&15, s = wid>>11;
    const float* qp = g_q   + ((size_t)b*128 + c)*1024;
    const float* kp = g_ksa + (size_t)(s*16+b)*1024;
    float acc = 0.f;
    for (int p=lane; p<1024; p+=32) acc += qp[p]*kp[p];
    #pragma unroll
    for (int o=16;o;o>>=1) acc += __shfl_down_sync(0xffffffffu, acc, o);
    if (!lane) g_qfg[wid] = acc*(1.f/1024.f);
}

// ---------------- s_prob[s,b,hw] = sigmoid( sum_c q_fg[s,b,c]*k[s,b,c,hw] ) ----------------
__global__ void sprob_k()
{
    int img = blockIdx.x;          // 128
    __shared__ float fq[128];
    int t = threadIdx.x;           // 256
    if (t < 128) fq[t] = g_qfg[img*128 + t];
    __syncthreads();
    for (int p=t; p<1024; p+=256){
        const float* kp = g_k + (size_t)img*CHW + p;
        float acc = 0.f;
        #pragma unroll 4
        for (int c=0;c<128;c++) acc += fq[c]*kp[(size_t)c<<10];
        g_sprob[img*1024 + p] = sigmf(acc);
    }
}

// ---------------- t logits: qg . kg over d = CH*HW ----------------
__global__ void tlogit_k()
{
    int img = blockIdx.x, b = img & 15;
    float acc = 0.f;
    for (int i=threadIdx.x; i<CHW; i+=256){
        int p = i & 1023;
        acc += g_q[(size_t)b*CHW + i]*g_qsa[b*1024+p]
             * g_k[(size_t)img*CHW + i]*g_ksa[img*1024+p];
    }
    #pragma unroll
    for (int o=16;o;o>>=1) acc += __shfl_down_sync(0xffffffffu, acc, o);
    __shared__ float sh[8];
    if ((threadIdx.x&31)==0) sh[threadIdx.x>>5] = acc;
    __syncthreads();
    if (threadIdx.x==0){
        float S=0.f;
        #pragma unroll
        for (int i=0;i<8;i++) S += sh[i];
        g_tl[img] = S * rsqrtf(131072.f);
    }
}

__global__ void tprob_k()
{
    int b = threadIdx.x;
    if (b >= 16) return;
    float m = -3.402823466e38f;
    #pragma unroll
    for (int s=0;s<8;s++) m = fmaxf(m, g_tl[s*16+b]);
    float e[8]; float sum = 0.f;
    #pragma unroll
    for (int s=0;s<8;s++){ e[s] = __expf(g_tl[s*16+b] - m); sum += e[s]; }
    float inv = 1.f/sum;
    #pragma unroll
    for (int s=0;s<8;s++) g_tp[s*16+b] = e[s]*inv;
}

// ---------------- av[b,c,hw] = sum_s t_prob[s,b] * s_prob[s,b,hw] * v[s,b,c,hw] ----------------
__global__ void av_k()
{
    int i = blockIdx.x*blockDim.x + threadIdx.x;   // float4 index
    if (i >= BN*CHW/4) return;
    int base = i<<2;
    int b = base>>17; int c = (base>>10)&127; int p = base&1023;
    float4 acc = make_float4(0.f,0.f,0.f,0.f);
    #pragma unroll
    for (int s=0;s<8;s++){
        int img = s*16 + b;
        float tw = g_tp[img];
        float4 sp = *(const float4*)&g_sprob[img*1024 + p];
        float4 vv = *(const float4*)&g_v[((size_t)img*128 + c)*1024 + p];
        acc.x += tw*sp.x*vv.x; acc.y += tw*sp.y*vv.y;
        acc.z += tw*sp.z*vv.z; acc.w += tw*sp.w*vv.w;
    }
    *(float4*)&g_av[base] = acc;
}

// ---------------- new_out = mask ? att : 0 (output region 2) ----------------
__global__ void newout_k(const unsigned char* __restrict__ mask, float* __restrict__ out)
{
    int i = blockIdx.x*blockDim.x + threadIdx.x;
    if (i >= BN*CHW/4) return;
    int base = i<<2;
    int b = base>>17;
    float4 v = mask_at(mask, b) ? *(const float4*)&g_att[base]
                                : make_float4(0.f,0.f,0.f,0.f);
    *(float4*)&out[(size_t)2*BN*CHW + base] = v;
}

// ---------------- SE block ----------------
__global__ void semean_k()
{
    int b = blockIdx.x;
    int w = threadIdx.x>>5, lane = threadIdx.x&31;
    for (int c=w; c<128; c+=8){
        const float* p = g_o + ((size_t)b*128 + c)*1024;
        float s = 0.f;
        for (int i=lane; i<1024; i+=32) s += p[i];
        #pragma unroll
        for (int o=16;o;o>>=1) s += __shfl_down_sync(0xffffffffu, s, o);
        if (!lane) g_se1[b*128+c] = s*(1.f/1024.f);
    }
}

__global__ void sefc1_k(const float* __restrict__ w1, const float* __restrict__ b1)
{
    int t = threadIdx.x;             // 512 = 16b * 32j
    int b = t>>5, j = t&31;
    float acc = b1[j];
    #pragma unroll 4
    for (int c=0;c<128;c++) acc += g_se1[b*128+c]*w1[j*128+c];
    g_se2[b*32+j] = fmaxf(acc, 0.f);
}

__global__ void sefc2_k(const float* __restrict__ w2, const float* __restrict__ b2)
{
    int i = blockIdx.x*blockDim.x + threadIdx.x;  // 2048 = 16b * 128c
    if (i >= BN*CH) return;
    int b = i>>7, c = i&127;
    float acc = b2[c];
    #pragma unroll
    for (int j=0;j<32;j++) acc += g_se2[b*32+j]*w2[c*32+j];
    g_se3[i] = sigmf(acc);
}

// ---------------- final: outputs = o*(1+g), also emit ht (regions 0,1) ----------------
__global__ void final_k(float* __restrict__ out)
{
    int i = blockIdx.x*blockDim.x + threadIdx.x;
    if (i >= BN*CHW/4) return;
    int base = i<<2;
    int b = base>>17; int c = (base>>10)&127;
    float g = 1.f + g_se3[b*128+c];
    float4 o4 = *(const float4*)&g_o[base];
    o4.x*=g; o4.y*=g; o4.z*=g; o4.w*=g;
    *(float4*)&out[base] = o4;
    *(float4*)&out[(size_t)BN*CHW + base] = *(const float4*)&g_ht[base];
}

// ---------------- host launcher ----------------
extern "C" void kernel_launch(void* const* d_in, const int* in_sizes, int n_in,
                              void* d_out, int out_size)
{
    (void)in_sizes; (void)n_in; (void)out_size;
    const float* inputs  = (const float*)d_in[0];
    const float* hidden  = (const float*)d_in[1];
    const float* outq    = (const float*)d_in[2];
    const unsigned char* mask = (const unsigned char*)d_in[3];
    const float* enc_w   = (const float*)d_in[4];
    const float* enc_gw  = (const float*)d_in[5];
    const float* enc_gb  = (const float*)d_in[6];
    const float* qpre_w  = (const float*)d_in[7];
    const float* qpre_gw = (const float*)d_in[8];
    const float* qpre_gb = (const float*)d_in[9];
    const float* kpre_w  = (const float*)d_in[10];
    const float* kpre_gw = (const float*)d_in[11];
    const float* kpre_gb = (const float*)d_in[12];
    const float* vpre_w  = (const float*)d_in[13];
    const float* vpre_gw = (const float*)d_in[14];
    const float* vpre_gb = (const float*)d_in[15];
    const float* qsa_w   = (const float*)d_in[16];
    const float* qsa_b   = (const float*)d_in[17];
    const float* ksa_w   = (const float*)d_in[18];
    const float* ksa_b   = (const float*)d_in[19];
    const float* vpost_w = (const float*)d_in[20];
    const float* vpost_gw= (const float*)d_in[21];
    const float* vpost_gb= (const float*)d_in[22];
    const float* pos_emb = (const float*)d_in[23];
    const float* outt_w  = (const float*)d_in[24];
    const float* outt_gw = (const float*)d_in[25];
    const float* outt_gb = (const float*)d_in[26];
    const float* se_w1   = (const float*)d_in[27];
    const float* se_b1   = (const float*)d_in[28];
    const float* se_w2   = (const float*)d_in[29];
    const float* se_b2   = (const float*)d_in[30];
    float* out = (float*)d_out;

    float *ht,*q,*k,*v,*av,*att,*o,*stats,*pool,*qsa,*ksa,*peN,*wT;
    cudaGetSymbolAddress((void**)&ht,   g_ht);
    cudaGetSymbolAddress((void**)&q,    g_q);
    cudaGetSymbolAddress((void**)&k,    g_k);
    cudaGetSymbolAddress((void**)&v,    g_v);
    cudaGetSymbolAddress((void**)&av,   g_av);
    cudaGetSymbolAddress((void**)&att,  g_att);
    cudaGetSymbolAddress((void**)&o,    g_o);
    cudaGetSymbolAddress((void**)&stats,g_stats);
    cudaGetSymbolAddress((void**)&pool, g_pool);
    cudaGetSymbolAddress((void**)&qsa,  g_qsa);
    cudaGetSymbolAddress((void**)&ksa,  g_ksa);
    cudaGetSymbolAddress((void**)&peN,  g_peN);
    cudaGetSymbolAddress((void**)&wT,   g_wT);

    // wT offsets
    const int OFF_ENC   = 0;        // 64*9*128   = 73728
    const int OFF_QPRE  = 73728;    // 128*9*128  = 147456
    const int OFF_KPRE  = 221184;   // 256*9*128  = 294912
    const int OFF_VPRE  = 516096;   // 256*9*128  = 294912
    const int OFF_OUTT  = 811008;   // 192*9*128  = 221184
    const int OFF_VPOST = 1032192;  // 128*1*128  = 16384

    transw_k<<<128,256>>>(enc_w,  wT+OFF_ENC,  64, 9);
    transw_k<<<256,256>>>(qpre_w, wT+OFF_QPRE, 128, 9);
    transw_k<<<512,256>>>(kpre_w, wT+OFF_KPRE, 256, 9);
    transw_k<<<512,256>>>(vpre_w, wT+OFF_VPRE, 256, 9);
    transw_k<<<384,256>>>(outt_w, wT+OFF_OUTT, 192, 9);
    transw_k<<<64,256>>>(vpost_w, wT+OFF_VPOST, 128, 1);
    pe_norm_k<<<8,256>>>(pos_emb, peN);

    // ht = silu(gn(conv(inputs, enc_w)))
    conv3x3_k<<<BN*8,256>>>(inputs, nullptr, nullptr, wT+OFF_ENC, ht, 64, 0);
    gn_reduce_k<<<BN,256>>>(ht, stats);
    gn_apply_k<<<2048,256>>>(ht, stats, enc_gw, enc_gb, BN, 1);

    // q = gn(conv(ht, qpre_w))
    conv3x3_k<<<BN*8,256>>>(ht, nullptr, nullptr, wT+OFF_QPRE, q, 128, 0);
    gn_reduce_k<<<BN,256>>>(q, stats);
    gn_apply_k<<<2048,256>>>(q, stats, qpre_gw, qpre_gb, BN, 0);

    // k = gn(conv(kv, kpre_w))
    conv3x3_k<<<SBN*8,256>>>(hidden, outq, nullptr, wT+OFF_KPRE, k, 256, 1);
    gn_reduce_k<<<SBN,256>>>(k, stats);
    gn_apply_k<<<4096,256>>>(k, stats, kpre_gw, kpre_gb, SBN, 0);

    // v = gn(conv(kv + pe, vpre_w))
    conv3x3_k<<<SBN*8,256>>>(hidden, outq, peN, wT+OFF_VPRE, v, 256, 2);
    gn_reduce_k<<<SBN,256>>>(v, stats);
    gn_apply_k<<<4096,256>>>(v, stats, vpre_gw, vpre_gb, SBN, 0);

    // spatial filters
    pool_k<<<(BN*HWN+255)/256,256>>>(q, pool, BN);
    saconv_k<<<(BN*HWN+255)/256,256>>>(pool, qsa_w, qsa_b, qsa, BN);
    pool_k<<<(SBN*HWN+255)/256,256>>>(k, pool, SBN);
    saconv_k<<<(SBN*HWN+255)/256,256>>>(pool, ksa_w, ksa_b, ksa, SBN);

    // attention pieces
    qfg_k<<<2048,256>>>();
    sprob_k<<<SBN,256>>>();
    tlogit_k<<<SBN,256>>>();
    tprob_k<<<1,32>>>();
    av_k<<<2048,256>>>();

    // att = silu(gn(conv1x1(av, vpost_w)))
    conv1x1_k<<<BN*8,256>>>(av, wT+OFF_VPOST, att);
    gn_reduce_k<<<BN,256>>>(att, stats);
    gn_apply_k<<<2048,256>>>(att, stats, vpost_gw, vpost_gb, BN, 1);

    // new_out (output region 2)
    newout_k<<<2048,256>>>(mask, out);

    // o = silu(gn(conv(concat(inputs, att+ht), outt_w)))
    conv3x3_k<<<BN*8,256>>>(inputs, att, ht, wT+OFF_OUTT, o, 192, 3);
    gn_reduce_k<<<BN,256>>>(o, stats);
    gn_apply_k<<<2048,256>>>(o, stats, outt_gw, outt_gb, BN, 1);

    // SE + final outputs (regions 0 and 1)
    semean_k<<<BN,256>>>();
    sefc1_k<<<1,512>>>(se_w1, se_b1);
    sefc2_k<<<8,256>>>(se_w2, se_b2);
    final_k<<<2048,256>>>(out);
}